// round 2
// baseline (speedup 1.0000x reference)
#include <cuda_runtime.h>

// ---------------- problem constants ----------------
#define O_    2
#define Z_    8
#define OY_   1024
#define P_    8
#define N_    256
#define NB_   32
#define NF    65536          // N_*N_
#define CP    257            // padded pitch (in float2) for column tiles
#define TWO_PI 6.28318530717958647692f

// ---------------- static device scratch ----------------
__device__ float2 g_tw[N_];                       // e^{+2*pi*i*k/256}
__device__ int    g_cy[NB_], g_cx[NB_];
__device__ float  g_sy[NB_], g_sx[NB_];
__device__ float2 g_probeF[(size_t)P_ * NF];                  // fft2(probe)
__device__ float2 g_probes[(size_t)NB_ * P_ * NF];            // shifted probes (spatial)
__device__ float2 g_bufA[(size_t)NB_ * O_ * P_ * NF];         // rowsA out / cols in
__device__ float2 g_bufB[(size_t)NB_ * O_ * P_ * NF];         // colsH out / rowsA in

// ---------------- complex helpers ----------------
__device__ __forceinline__ float2 cadd(float2 a, float2 b){ return make_float2(a.x+b.x, a.y+b.y); }
__device__ __forceinline__ float2 csub(float2 a, float2 b){ return make_float2(a.x-b.x, a.y-b.y); }
__device__ __forceinline__ float2 cmul(float2 a, float2 b){ return make_float2(a.x*b.x - a.y*b.y, a.x*b.y + a.y*b.x); }

// ---------------- warp-private 256-pt Stockham radix-4 FFT ----------------
// buf: 256 contiguous float2 in shared memory, touched only by this warp.
// DIR = -1 forward (e^{-i}), +1 inverse (unscaled).
// In-place is safe: all 64 butterflies are read into registers (8 pts/thread)
// before any write, with __syncwarp between the phases.
template<int DIR>
__device__ __forceinline__ void warp_fft256(float2* buf, int lane, const float2* tw){
    int s = 1;
    #pragma unroll
    for (int st = 0; st < 4; st++){
        int m = 64 / s;
        float2 v[2][4];
        int pb[2], qb[2];
        #pragma unroll
        for (int h = 0; h < 2; h++){
            int u = lane + 32*h;
            int p = u / s;
            int q = u - p*s;
            pb[h] = p; qb[h] = q;
            #pragma unroll
            for (int k = 0; k < 4; k++)
                v[h][k] = buf[q + s*(p + k*m)];
        }
        __syncwarp();
        #pragma unroll
        for (int h = 0; h < 2; h++){
            int p = pb[h], q = qb[h];
            float2 a = v[h][0], b = v[h][1], c = v[h][2], d = v[h][3];
            float2 apc = cadd(a,c), amc = csub(a,c);
            float2 bpd = cadd(b,d), bmd = csub(b,d);
            // DIR * j * (b-d)
            float2 jb = make_float2(-(float)DIR * bmd.y, (float)DIR * bmd.x);
            float2 y0 = cadd(apc, bpd);
            float2 t1 = cadd(amc, jb);
            float2 y2 = csub(apc, bpd);
            float2 t3 = csub(amc, jb);
            int k1 = p*s;
            float2 w1 = tw[k1];     w1.y *= (float)DIR;
            float2 w2 = tw[2*k1];   w2.y *= (float)DIR;
            float2 w3 = tw[3*k1];   w3.y *= (float)DIR;
            int ob = q + s*4*p;
            buf[ob        ] = y0;
            buf[ob +   s  ] = cmul(w1, t1);
            buf[ob + 2*s  ] = cmul(w2, y2);
            buf[ob + 3*s  ] = cmul(w3, t3);
        }
        __syncwarp();
        s *= 4;
    }
}

// ---------------- setup: twiddles + index resolution ----------------
__global__ void k_setup(const float* __restrict__ shifts,
                        const int*   __restrict__ crop,
                        const void*  __restrict__ idxraw){
    int t = threadIdx.x;
    if (t < N_){
        double ang = 2.0 * 3.14159265358979323846 * (double)t / (double)N_;
        g_tw[t] = make_float2((float)cos(ang), (float)sin(ang));
    }
    if (t == 0){
        // dtype detection: safe 128B read either way (NB_=32 int32 words)
        const int* w = (const int*)idxraw;
        int orr = 0;
        for (int k = 1; k < NB_; k += 2) orr |= w[k];
        bool is64 = (orr == 0);
        for (int b = 0; b < NB_; b++){
            int id = is64 ? (int)(((const long long*)idxraw)[b]) : w[b];
            g_cy[b] = crop[2*id];
            g_cx[b] = crop[2*id + 1];
            g_sy[b] = shifts[2*id];
            g_sx[b] = shifts[2*id + 1];
        }
    }
}

// ---------------- probe forward FFT: rows ----------------
__global__ void k_probe_rows(const float* __restrict__ pr, const float* __restrict__ pi){
    // grid P_*32, 256 threads; warp per row, 8 rows per CTA
    int blk = blockIdx.x, rblk = blk & 31, p = blk >> 5;
    int w = threadIdx.x >> 5, lane = threadIdx.x & 31;
    int y = rblk*8 + w;
    __shared__ float2 fb[8][N_];
    __shared__ float2 tw[N_];
    for (int i = threadIdx.x; i < N_; i += 256) tw[i] = g_tw[i];
    __syncthreads();
    size_t base = ((size_t)p * N_ + y) * N_;
    for (int xx = lane; xx < N_; xx += 32)
        fb[w][xx] = make_float2(pr[base+xx], pi[base+xx]);
    __syncwarp();
    warp_fft256<-1>(fb[w], lane, tw);
    for (int xx = lane; xx < N_; xx += 32)
        g_probeF[base+xx] = fb[w][xx];
}

// ---------------- probe forward FFT: cols (in place) ----------------
__global__ void k_probe_cols(){
    // grid P_*16, 512 threads; warp per column, 16-col tile
    int blk = blockIdx.x, tile = blk & 15, p = blk >> 4;
    int xg0 = tile*16;
    int w = threadIdx.x >> 5, lane = threadIdx.x & 31;
    __shared__ float2 sh[16*CP];
    __shared__ float2 tw[N_];
    for (int i = threadIdx.x; i < N_; i += 512) tw[i] = g_tw[i];
    float2* fld = g_probeF + (size_t)p * NF;
    for (int i = threadIdx.x; i < 4096; i += 512){
        int yy = i >> 4, xx = i & 15;
        sh[xx*CP + yy] = fld[(size_t)yy*N_ + xg0 + xx];
    }
    __syncthreads();
    warp_fft256<-1>(sh + w*CP, lane, tw);
    __syncthreads();
    for (int i = threadIdx.x; i < 4096; i += 512){
        int yy = i >> 4, xx = i & 15;
        fld[(size_t)yy*N_ + xg0 + xx] = sh[xx*CP + yy];
    }
}

// ---------------- shifted probes: ramp multiply + row inverse FFT ----------------
__global__ void k_probes_rows(){
    // grid NB_*P_*32, 256 threads
    int blk = blockIdx.x, rblk = blk & 31, bp = blk >> 5;
    int p = bp & 7, b = bp >> 3;
    int w = threadIdx.x >> 5, lane = threadIdx.x & 31;
    int y = rblk*8 + w;
    __shared__ float2 fb[8][N_];
    __shared__ float2 tw[N_];
    for (int i = threadIdx.x; i < N_; i += 256) tw[i] = g_tw[i];
    __syncthreads();
    float sy = g_sy[b], sx = g_sx[b];
    float angy = -(TWO_PI / N_) * sy * (float)y;
    size_t base = ((size_t)p * N_ + y) * N_;
    const float invn = 1.0f / N_;
    for (int xx = lane; xx < N_; xx += 32){
        float ang = angy - (TWO_PI / N_) * sx * (float)xx;
        float sn, cs;
        sincosf(ang, &sn, &cs);                 // large args -> accurate version
        float2 r = make_float2(cs*invn, sn*invn); // fold row-inverse 1/N
        fb[w][xx] = cmul(g_probeF[base+xx], r);
    }
    __syncwarp();
    warp_fft256<+1>(fb[w], lane, tw);
    float2* dst = g_probes + ((size_t)b*P_ + p) * NF + (size_t)y * N_;
    for (int xx = lane; xx < N_; xx += 32) dst[xx] = fb[w][xx];
}

// ---------------- shifted probes: col inverse FFT (in place, scaled) ----------------
__global__ void k_cols_inv(){
    // grid NB_*P_*16, 512 threads
    int blk = blockIdx.x, tile = blk & 15, f = blk >> 4;
    int xg0 = tile*16;
    int w = threadIdx.x >> 5, lane = threadIdx.x & 31;
    __shared__ float2 sh[16*CP];
    __shared__ float2 tw[N_];
    for (int i = threadIdx.x; i < N_; i += 512) tw[i] = g_tw[i];
    float2* fld = g_probes + (size_t)f * NF;
    for (int i = threadIdx.x; i < 4096; i += 512){
        int yy = i >> 4, xx = i & 15;
        sh[xx*CP + yy] = fld[(size_t)yy*N_ + xg0 + xx];
    }
    __syncthreads();
    warp_fft256<+1>(sh + w*CP, lane, tw);
    __syncthreads();
    const float invn = 1.0f / N_;
    for (int i = threadIdx.x; i < 4096; i += 512){
        int yy = i >> 4, xx = i & 15;
        float2 v = sh[xx*CP + yy];
        fld[(size_t)yy*N_ + xg0 + xx] = make_float2(v.x*invn, v.y*invn);
    }
}

// ---------------- rows pass A: [row-IFFT] -> x obj[z] -> row-FFT, writes pp ----------------
__global__ void k_rows_A(const float* __restrict__ obja, const float* __restrict__ objp,
                         float* __restrict__ pp_out, int z){
    // grid NB_*O_*32, 256 threads; warp per row, loops p (obj shared across P)
    int blk = blockIdx.x, rblk = blk & 31, bo = blk >> 5;
    int o = bo & 1, b = bo >> 1;
    int w = threadIdx.x >> 5, lane = threadIdx.x & 31;
    int y = rblk*8 + w;
    __shared__ float2 objsh[8][N_];
    __shared__ float2 fb[8][N_];
    __shared__ float2 tw[N_];
    for (int i = threadIdx.x; i < N_; i += 256) tw[i] = g_tw[i];

    int cy = g_cy[b], cx = g_cx[b];
    size_t obase = (((size_t)(o*Z_ + z)) * OY_ + (size_t)(cy + y)) * OY_ + cx;
    float scale = (z == 0) ? 1.0f : (1.0f / N_);   // fold row-IFFT 1/N into obj
    size_t ppbase = ((((size_t)b*O_ + o)*Z_ + z) * N_ + y) * (size_t)N_;
    for (int xx = lane; xx < N_; xx += 32){
        float A  = obja[obase + xx];
        float ph = objp[obase + xx];
        float sn, cs;
        __sincosf(ph, &sn, &cs);                   // |ph| small -> fast intrinsic OK
        objsh[w][xx] = make_float2(A*cs*scale, A*sn*scale);
        pp_out[ppbase + xx] = ph;
    }
    __syncthreads();

    for (int p = 0; p < P_; p++){
        const float2* src = (z == 0)
            ? (g_probes + ((size_t)b*P_ + p) * NF + (size_t)y * N_)
            : (g_bufB  + ((size_t)bo*P_ + p) * NF + (size_t)y * N_);
        for (int xx = lane; xx < N_; xx += 32) fb[w][xx] = src[xx];
        __syncwarp();
        if (z) warp_fft256<+1>(fb[w], lane, tw);
        for (int xx = lane; xx < N_; xx += 32)
            fb[w][xx] = cmul(fb[w][xx], objsh[w][xx]);
        __syncwarp();
        warp_fft256<-1>(fb[w], lane, tw);
        float2* dst = g_bufA + ((size_t)bo*P_ + p) * NF + (size_t)y * N_;
        for (int xx = lane; xx < N_; xx += 32) dst[xx] = fb[w][xx];
        __syncwarp();
    }
}

// ---------------- cols pass B: col-FFT -> x H -> col-IFFT ----------------
__global__ void k_cols_H(const float* __restrict__ Hr, const float* __restrict__ Hi){
    // grid NB_*O_*P_*16, 512 threads
    int blk = blockIdx.x, tile = blk & 15, f = blk >> 4;
    int xg0 = tile*16;
    int w = threadIdx.x >> 5, lane = threadIdx.x & 31;
    __shared__ float2 sh[16*CP];
    __shared__ float2 tw[N_];
    for (int i = threadIdx.x; i < N_; i += 512) tw[i] = g_tw[i];
    const float2* s = g_bufA + (size_t)f * NF;
    for (int i = threadIdx.x; i < 4096; i += 512){
        int yy = i >> 4, xx = i & 15;
        sh[xx*CP + yy] = s[(size_t)yy*N_ + xg0 + xx];
    }
    __syncthreads();
    float2* cb = sh + w*CP;
    warp_fft256<-1>(cb, lane, tw);
    const float invn = 1.0f / N_;                  // fold col-IFFT 1/N into H
    int xg = xg0 + w;
    for (int yy = lane; yy < N_; yy += 32){
        float2 h = make_float2(Hr[yy*N_ + xg] * invn, Hi[yy*N_ + xg] * invn);
        cb[yy] = cmul(cb[yy], h);
    }
    __syncwarp();
    warp_fft256<+1>(cb, lane, tw);
    __syncthreads();
    float2* d = g_bufB + (size_t)f * NF;
    for (int i = threadIdx.x; i < 4096; i += 512){
        int yy = i >> 4, xx = i & 15;
        d[(size_t)yy*N_ + xg0 + xx] = sh[xx*CP + yy];
    }
}

// ---------------- final: col-FFT -> weighted |.|^2 accumulation -> dp (fftshift) ----------------
__global__ void k_cols_final(const float* __restrict__ occu, float* __restrict__ dp){
    // grid NB_*16, 512 threads; accumulates over o (2) and p (8) per tile
    int blk = blockIdx.x, tile = blk & 15, b = blk >> 4;
    int xg0 = tile*16;
    int w = threadIdx.x >> 5, lane = threadIdx.x & 31;
    __shared__ float2 sh[16*CP];
    __shared__ float2 tw[N_];
    for (int i = threadIdx.x; i < N_; i += 512) tw[i] = g_tw[i];
    float acc[8];
    #pragma unroll
    for (int k = 0; k < 8; k++) acc[k] = 0.0f;

    for (int o = 0; o < O_; o++){
        float wt = occu[o];
        for (int p = 0; p < P_; p++){
            const float2* s = g_bufA + ((size_t)((b*O_ + o)*P_ + p)) * NF;
            __syncthreads();                        // protect sh from previous iteration
            for (int i = threadIdx.x; i < 4096; i += 512){
                int yy = i >> 4, xx = i & 15;
                sh[xx*CP + yy] = s[(size_t)yy*N_ + xg0 + xx];
            }
            __syncthreads();
            float2* cb = sh + w*CP;
            warp_fft256<-1>(cb, lane, tw);
            #pragma unroll
            for (int k = 0; k < 8; k++){
                float2 v = cb[lane + 32*k];
                acc[k] += wt * (v.x*v.x + v.y*v.y);
            }
        }
    }
    // stage accumulators through shared for coalesced, fftshifted writes
    __syncthreads();
    float* shf = (float*)sh;
    #pragma unroll
    for (int k = 0; k < 8; k++) shf[w*CP*2 + lane + 32*k] = acc[k];
    __syncthreads();
    int xs0 = (xg0 + 128) & 255;
    for (int i = threadIdx.x; i < 4096; i += 512){
        int yy = i >> 4, xx = i & 15;
        int ys = (yy + 128) & 255;
        dp[(size_t)b*NF + (size_t)ys*N_ + xs0 + xx] = shf[xx*CP*2 + yy];
    }
}

// ---------------- launch ----------------
extern "C" void kernel_launch(void* const* d_in, const int* in_sizes, int n_in,
                              void* d_out, int out_size){
    const float* obja   = (const float*)d_in[0];
    const float* objp   = (const float*)d_in[1];
    const float* pr     = (const float*)d_in[2];
    const float* pi     = (const float*)d_in[3];
    const float* Hr     = (const float*)d_in[4];
    const float* Hi     = (const float*)d_in[5];
    const float* occu   = (const float*)d_in[6];
    const float* shifts = (const float*)d_in[7];
    const int*   crop   = (const int*)d_in[8];
    const void*  idx    = d_in[9];

    float* dp = (float*)d_out;                    // (NB, 256, 256)
    float* pp = dp + (size_t)NB_ * NF;            // (NB, O, Z, 256, 256)

    k_setup<<<1, 256>>>(shifts, crop, idx);
    k_probe_rows<<<P_*32, 256>>>(pr, pi);
    k_probe_cols<<<P_*16, 512>>>();
    k_probes_rows<<<NB_*P_*32, 256>>>();
    k_cols_inv<<<NB_*P_*16, 512>>>();

    k_rows_A<<<NB_*O_*32, 256>>>(obja, objp, pp, 0);
    for (int z = 0; z < Z_ - 1; z++){
        k_cols_H<<<NB_*O_*P_*16, 512>>>(Hr, Hi);
        k_rows_A<<<NB_*O_*32, 256>>>(obja, objp, pp, z + 1);
    }
    k_cols_final<<<NB_*16, 512>>>(occu, dp);
}